// round 15
// baseline (speedup 1.0000x reference)
#include <cuda_runtime.h>
#include <cuda_fp16.h>
#include <cstdint>

#define BATCH   2048
#define IN_DIM  4096
#define OUT_DIM 4096

__device__ __align__(256) __half g_W_h[(size_t)IN_DIM * OUT_DIM];   // [K,N] fp16
__device__ __align__(256) __half g_A_h[(size_t)BATCH * IN_DIM];     // [M,K] fp16
// FMA-column transpose: layout [k8][512 cols][8 halves] (16B per (k8,col))
__device__ __align__(256) __half g_Wt_h[(size_t)(IN_DIM / 8) * 512 * 8];
__device__ int g_ticket, g_fma_ticket, g_dec_ticket, g_a_done, g_chunks_done, g_done;
__device__ __align__(16) int g_slab_done[128];

#define NWORKERS 296
#define N_T 3584                 // tensor columns
#define BM 128
#define BN 64
#define BK 32
#define KT 128
#define NT_T ((BATCH / BM) * (N_T / BN))   // 896
#define NT_F ((BATCH / 8) * 2)             // 512 (8 rows x 256 cols each)
#define STAGES 4
#define LDA_S 40
#define LDB_S 72
#define A_STAGE_H (BM * LDA_S)   // 5120
#define B_STAGE_H (BK * LDB_S)   // 2304
#define STAGE_H   (A_STAGE_H + B_STAGE_H)
#define SMEM_BYTES (STAGES * STAGE_H * 2)  // 59392

#define NDEC 128
#define NCHUNKS 512
#define CHUNK_INT4 8192
#define A_UNITS (BATCH * IN_DIM / 8)
#define A_PER_CTA ((A_UNITS + NWORKERS - 1) / NWORKERS)

__device__ __forceinline__ uint32_t smem_u32(const void* p) {
    uint32_t a;
    asm("{ .reg .u64 t; cvta.to.shared.u64 t, %1; cvt.u32.u64 %0, t; }" : "=r"(a) : "l"(p));
    return a;
}
__device__ __forceinline__ void cp_async16(__half* d, const __half* s) {
    uint32_t a = (uint32_t)__cvta_generic_to_shared(d);
    asm volatile("cp.async.cg.shared.global [%0], [%1], 16;\n" :: "r"(a), "l"(s));
}
__device__ __forceinline__ void mbar_init(uint32_t b, uint32_t c) {
    asm volatile("mbarrier.init.shared.b64 [%0], %1;" :: "r"(b), "r"(c) : "memory");
}
__device__ __forceinline__ void mbar_arrive(uint32_t b) {
    asm volatile("mbarrier.arrive.shared.b64 _, [%0];" :: "r"(b) : "memory");
}
__device__ __forceinline__ void cpasync_mbar_arrive(uint32_t b) {
    asm volatile("cp.async.mbarrier.arrive.noinc.shared.b64 [%0];" :: "r"(b) : "memory");
}
__device__ __forceinline__ void mbar_wait(uint32_t b, uint32_t par) {
    uint32_t done;
    asm volatile(
        "{\n\t.reg .pred p;\n\t"
        "mbarrier.try_wait.parity.acquire.cta.shared::cta.b64 p, [%1], %2;\n\t"
        "selp.b32 %0, 1, 0, p;\n\t}" : "=r"(done) : "r"(b), "r"(par) : "memory");
    if (!done) {
        asm volatile(
            "{\n\t.reg .pred P1;\n\t"
            "WL_%=:\n\t"
            "mbarrier.try_wait.parity.acquire.cta.shared::cta.b64 P1, [%0], %1, 0x989680;\n\t"
            "@P1 bra.uni WD_%=;\n\t"
            "bra.uni WL_%=;\n\t"
            "WD_%=:\n\t}" :: "r"(b), "r"(par) : "memory");
    }
}
__device__ __forceinline__ void named_bar(int id, int cnt) {
    asm volatile("bar.sync %0, %1;" :: "r"(id), "r"(cnt) : "memory");
}
__device__ __forceinline__ void ldmatrix_x4(uint32_t* r, const __half* p) {
    uint32_t a = (uint32_t)__cvta_generic_to_shared(p);
    asm volatile("ldmatrix.sync.aligned.m8n8.x4.shared.b16 {%0,%1,%2,%3}, [%4];"
                 : "=r"(r[0]), "=r"(r[1]), "=r"(r[2]), "=r"(r[3]) : "r"(a));
}
__device__ __forceinline__ void ldmatrix_x4_trans(uint32_t* r, const __half* p) {
    uint32_t a = (uint32_t)__cvta_generic_to_shared(p);
    asm volatile("ldmatrix.sync.aligned.m8n8.x4.trans.shared.b16 {%0,%1,%2,%3}, [%4];"
                 : "=r"(r[0]), "=r"(r[1]), "=r"(r[2]), "=r"(r[3]) : "r"(a));
}
__device__ __forceinline__ void mma_16816(float* d, const uint32_t* a, const uint32_t* b) {
    asm volatile(
        "mma.sync.aligned.m16n8k16.row.col.f32.f16.f16.f32 "
        "{%0,%1,%2,%3}, {%4,%5,%6,%7}, {%8,%9}, {%0,%1,%2,%3};"
        : "+f"(d[0]), "+f"(d[1]), "+f"(d[2]), "+f"(d[3])
        : "r"(a[0]), "r"(a[1]), "r"(a[2]), "r"(a[3]), "r"(b[0]), "r"(b[1]));
}
__device__ __forceinline__ int ld_acq(const int* p) {
    int v;
    asm volatile("ld.acquire.gpu.global.s32 %0, [%1];" : "=r"(v) : "l"(p) : "memory");
    return v;
}
__device__ __forceinline__ void spin_pause() { asm volatile("nanosleep.u32 64;" ::); }

__global__ __launch_bounds__(128, 2) void fused_kernel(
    const int4* __restrict__ idx, const float* __restrict__ mean,
    const float4* __restrict__ x, const float* __restrict__ bias,
    float* __restrict__ out)
{
    extern __shared__ __half smem[];
    __shared__ int s_tile_t, s_tile_f, s_chunk;
    __shared__ __align__(8) uint64_t s_mbar[2 * STAGES];
    __shared__ float s_mean[IN_DIM];

    const int cta = blockIdx.x;
    const int tid = threadIdx.x;
    const int lane = tid & 31;
    const int wid  = tid >> 5;

    // ---- Phase A: convert x -> fp16 (all CTAs) ----
    {
        const int u0 = cta * A_PER_CTA;
        const int u1 = (u0 + A_PER_CTA < A_UNITS) ? u0 + A_PER_CTA : A_UNITS;
        for (int u = u0 + tid; u < u1; u += 128) {
            float4 v0 = x[2 * u], v1 = x[2 * u + 1];
            __half2 h0 = __floats2half2_rn(v0.x, v0.y), h1 = __floats2half2_rn(v0.z, v0.w);
            __half2 h2 = __floats2half2_rn(v1.x, v1.y), h3 = __floats2half2_rn(v1.z, v1.w);
            uint4 pk;
            pk.x = *(uint32_t*)&h0; pk.y = *(uint32_t*)&h1;
            pk.z = *(uint32_t*)&h2; pk.w = *(uint32_t*)&h3;
            reinterpret_cast<uint4*>(g_A_h)[u] = pk;
        }
        __threadfence();
        __syncthreads();
        if (tid == 0) atomicAdd(&g_a_done, 1);
    }

    // ---- Phase W: decode (CTAs < NDEC), also writes g_Wt for FMA columns ----
    if (cta < NDEC) {
        for (int i = tid; i < IN_DIM; i += 128) s_mean[i] = mean[i];
        __syncthreads();
        while (true) {
            if (tid == 0) s_chunk = atomicAdd(&g_dec_ticket, 1);
            __syncthreads();
            const int cc = s_chunk;
            if (cc >= NCHUNKS) break;
            const size_t base = (size_t)cc * CHUNK_INT4 + tid;
            #pragma unroll 4
            for (int g = 0; g < CHUNK_INT4 / (128 * 4); g++) {
                #pragma unroll
                for (int j = 0; j < 4; j++) {
                    const int local = tid + (g * 4 + j) * 128;
                    int4 v = idx[base + (size_t)(g * 4 + j) * 128];
                    __half ha = __float2half_rn(s_mean[v.x]);
                    __half hb = __float2half_rn(s_mean[v.y]);
                    __half hc = __float2half_rn(s_mean[v.z]);
                    __half hd = __float2half_rn(s_mean[v.w]);
                    __half2 lo = __halves2half2(ha, hb), hi = __halves2half2(hc, hd);
                    uint2 pk;
                    pk.x = *(uint32_t*)&lo; pk.y = *(uint32_t*)&hi;
                    reinterpret_cast<uint2*>(g_W_h)[base + (size_t)(g * 4 + j) * 128] = pk;
                    const int n0 = (local & 1023) * 4;
                    if (n0 >= N_T) {
                        const int krow = cc * 8 + (local >> 10);
                        const size_t wb = ((size_t)(krow >> 3) * 512 + (n0 - N_T)) * 8 + (krow & 7);
                        g_Wt_h[wb]      = ha;
                        g_Wt_h[wb + 8]  = hb;
                        g_Wt_h[wb + 16] = hc;
                        g_Wt_h[wb + 24] = hd;
                    }
                }
            }
            __threadfence();
            __syncthreads();
            if (tid == 0) {
                atomicAdd(&g_slab_done[cc >> 2], 1);
                atomicAdd(&g_chunks_done, 1);
            }
        }
        __syncthreads();
    }

    // ---- mbarrier init (tensor ring, 64 arrivals), then role split ----
    const uint32_t mb = smem_u32(s_mbar);
    if (tid == 0) {
        #pragma unroll
        for (int s = 0; s < STAGES; s++) {
            mbar_init(mb + s * 8, 64);                // full
            mbar_init(mb + (STAGES + s) * 8, 64);     // empty
        }
    }
    __syncthreads();

    // Per-thread readiness gates
    int wmax = -1; bool wall = false;
    auto gate_slab = [&](int s) {
        if (s <= wmax) return;
        if (ld_acq(&g_chunks_done) >= NCHUNKS) { wmax = 127; wall = true; return; }
        while (ld_acq(&g_slab_done[s]) < 4) spin_pause();
        wmax = s;
    };
    while (ld_acq(&g_a_done) < NWORKERS) spin_pause();

    const bool flip = (cta >= 148);
    const bool is_tensor = ((wid >> 1) == (flip ? 1 : 0));

    if (is_tensor) {
        // =================== TENSOR: 2 warps, 128x64 tile ===================
        const int tw = wid & 1;
        const int ttid = tw * 32 + lane;
        const int lrow = lane & 15, lcol = (lane >> 4) * 8;
        auto full_bar  = [&](int s) -> uint32_t { return mb + s * 8; };
        auto empty_bar = [&](int s) -> uint32_t { return mb + (STAGES + s) * 8; };
        auto As = [&](int s) { return smem + s * STAGE_H; };
        auto Bs = [&](int s) { return smem + s * STAGE_H + A_STAGE_H; };
        int ps = 0, pp = 1, cs = 0, cp = 0;

        auto produce = [&](int kt, int row0, int col0) {
            gate_slab(kt);
            mbar_wait(empty_bar(ps), (uint32_t)pp);
            const __half* Ag = g_A_h + (size_t)row0 * IN_DIM + kt * BK;
            const __half* Bg = g_W_h + (size_t)(kt * BK) * OUT_DIM + col0;
            __half* as = As(ps);
            __half* bs = Bs(ps);
            #pragma unroll
            for (int p = 0; p < 8; p++) {
                int f = ttid + p * 64, r = f >> 2, c = (f & 3) * 8;
                cp_async16(&as[r * LDA_S + c], Ag + (size_t)r * IN_DIM + c);
            }
            #pragma unroll
            for (int p = 0; p < 4; p++) {
                int f = ttid + p * 64, r = f >> 3, c = (f & 7) * 8;
                cp_async16(&bs[r * LDB_S + c], Bg + (size_t)r * OUT_DIM + c);
            }
            cpasync_mbar_arrive(full_bar(ps));
            if (++ps == STAGES) { ps = 0; pp ^= 1; }
        };
        auto fetch = [&]() -> int {
            named_bar(2, 64);
            if (ttid == 0) s_tile_t = atomicAdd(&g_ticket, 1);
            named_bar(2, 64);
            return s_tile_t;
        };

        int t = fetch();
        if (t < NT_T) {
            int row0 = (t / 56) * BM, col0 = (t % 56) * BN;
            #pragma unroll
            for (int s = 0; s < STAGES - 1; s++) produce(s, row0, col0);
            while (true) {
                float acc[4][8][4];
                #pragma unroll
                for (int i = 0; i < 4; i++)
                    #pragma unroll
                    for (int j = 0; j < 8; j++)
                        #pragma unroll
                        for (int e = 0; e < 4; e++) acc[i][j][e] = 0.0f;

                for (int kt = 0; kt < KT; kt++) {
                    if (kt + STAGES - 1 < KT) produce(kt + STAGES - 1, row0, col0);
                    mbar_wait(full_bar(cs), (uint32_t)cp);
                    const __half* Asb = As(cs);
                    const __half* Bsb = Bs(cs);
                    uint32_t afr[2][4][4], bfr[2][4][4];
                    #pragma unroll
                    for (int ks = 0; ks < 2; ks++) {
                        #pragma unroll
                        for (int mt = 0; mt < 4; mt++)
                            ldmatrix_x4(afr[ks][mt],
                                Asb + (tw * 64 + mt * 16 + lrow) * LDA_S + ks * 16 + lcol);
                        #pragma unroll
                        for (int nt2 = 0; nt2 < 4; nt2++)
                            ldmatrix_x4_trans(bfr[ks][nt2],
                                Bsb + (ks * 16 + lrow) * LDB_S + nt2 * 16 + lcol);
                    }
                    mbar_arrive(empty_bar(cs));
                    if (++cs == STAGES) { cs = 0; cp ^= 1; }
                    #pragma unroll
                    for (int ks = 0; ks < 2; ks++)
                        #pragma unroll
                        for (int mt = 0; mt < 4; mt++)
                            #pragma unroll
                            for (int nt = 0; nt < 8; nt++)
                                mma_16816(acc[mt][nt], afr[ks][mt],
                                          &bfr[ks][nt >> 1][(nt & 1) * 2]);
                }

                const int erow0 = row0, ecol0 = col0;
                int t2 = fetch();
                const bool more = (t2 < NT_T);
                if (more) {
                    row0 = (t2 / 56) * BM; col0 = (t2 % 56) * BN;
                    #pragma unroll
                    for (int s = 0; s < STAGES - 1; s++) produce(s, row0, col0);
                }
                #pragma unroll
                for (int mt = 0; mt < 4; mt++) {
                    const int r = erow0 + tw * 64 + mt * 16 + (lane >> 2);
                    float* o0 = out + (size_t)r * OUT_DIM;
                    float* o1 = out + (size_t)(r + 8) * OUT_DIM;
                    #pragma unroll
                    for (int nt = 0; nt < 8; nt++) {
                        const int c = ecol0 + nt * 8 + 2 * (lane & 3);
                        float2 bb = *reinterpret_cast<const float2*>(bias + c);
                        float2 v0 = { acc[mt][nt][0] + bb.x, acc[mt][nt][1] + bb.y };
                        float2 v1 = { acc[mt][nt][2] + bb.x, acc[mt][nt][3] + bb.y };
                        *reinterpret_cast<float2*>(o0 + c) = v0;
                        *reinterpret_cast<float2*>(o1 + c) = v1;
                    }
                }
                if (!more) break;
            }
        }
    } else {
        // =================== FMA: 2 warps, cols [3584,4096) =================
        const int fw = wid & 1;
        const uint4* Wt4 = reinterpret_cast<const uint4*>(g_Wt_h);
        while (true) {
            named_bar(3, 64);
            if (fw == 0 && lane == 0) s_tile_f = atomicAdd(&g_fma_ticket, 1);
            named_bar(3, 64);
            const int t = s_tile_f;
            if (t >= NT_F) break;
            const int r0 = (t >> 1) * 8;
            const int colrel = (t & 1) * 256 + fw * 128 + lane;  // + cidx*32

            float accf[8][4];
            #pragma unroll
            for (int r = 0; r < 8; r++)
                #pragma unroll
                for (int ci = 0; ci < 4; ci++) accf[r][ci] = 0.0f;

            for (int kc = 0; kc < 128; kc++) {      // 32-k chunks; slab == kc
                gate_slab(kc);
                __half2 acch[8][4];
                #pragma unroll
                for (int r = 0; r < 8; r++)
                    #pragma unroll
                    for (int ci = 0; ci < 4; ci++)
                        acch[r][ci] = __float2half2_rn(0.0f);
                #pragma unroll
                for (int k8 = 0; k8 < 4; k8++) {
                    const int k0 = kc * 32 + k8 * 8;
                    uint4 b4[4], a4[8];
                    #pragma unroll
                    for (int ci = 0; ci < 4; ci++)
                        b4[ci] = __ldg(&Wt4[(size_t)(k0 >> 3) * 512 + colrel + ci * 32]);
                    #pragma unroll
                    for (int r = 0; r < 8; r++)
                        a4[r] = __ldg(reinterpret_cast<const uint4*>(
                                    g_A_h + (size_t)(r0 + r) * IN_DIM + k0));
                    #pragma unroll
                    for (int k2 = 0; k2 < 4; k2++)
                        #pragma unroll
                        for (int r = 0; r < 8; r++) {
                            const __half2 a2 = reinterpret_cast<const __half2*>(&a4[r])[k2];
                            #pragma unroll
                            for (int ci = 0; ci < 4; ci++)
                                acch[r][ci] = __hfma2(a2,
                                    reinterpret_cast<const __half2*>(&b4[ci])[k2],
                                    acch[r][ci]);
                        }
                }
                #pragma unroll
                for (int r = 0; r < 8; r++)
                    #pragma unroll
                    for (int ci = 0; ci < 4; ci++) {
                        float2 f = __half22float2(acch[r][ci]);
                        accf[r][ci] += f.x + f.y;
                    }
            }
            // Epilogue: col = 3584 + colrel + ci*32 (lane-contiguous stores)
            #pragma unroll
            for (int ci = 0; ci < 4; ci++) {
                const int c = N_T + colrel + ci * 32;
                const float bb = __ldg(bias + c);
                #pragma unroll
                for (int r = 0; r < 8; r++)
                    out[(size_t)(r0 + r) * OUT_DIM + c] = accf[r][ci] + bb;
            }
        }
    }

    // ---- Reset (last CTA out) ----
    __syncthreads();
    if (tid == 0) {
        __threadfence();
        int d = atomicAdd(&g_done, 1);
        if (d == NWORKERS - 1) {
            g_ticket = 0; g_fma_ticket = 0; g_dec_ticket = 0;
            g_a_done = 0; g_chunks_done = 0;
            #pragma unroll
            for (int s = 0; s < 128; s++) g_slab_done[s] = 0;
            __threadfence();
            g_done = 0;
            __threadfence();
        }
    }
}

extern "C" void kernel_launch(void* const* d_in, const int* in_sizes, int n_in,
                              void* d_out, int out_size) {
    const float* xf   = (const float*)d_in[0];
    const int*   idx  = (const int*)  d_in[1];
    const float* mean = (const float*)d_in[2];
    const float* bias = (const float*)d_in[3];
    float* out = (float*)d_out;

    cudaFuncSetAttribute(fused_kernel,
                         cudaFuncAttributeMaxDynamicSharedMemorySize, SMEM_BYTES);
    fused_kernel<<<NWORKERS, 128, SMEM_BYTES>>>(
        (const int4*)idx, mean, (const float4*)xf, bias, out);
}

// round 16
// speedup vs baseline: 1.2053x; 1.2053x over previous
#include <cuda_runtime.h>
#include <cuda_fp16.h>
#include <cstdint>

#define BATCH   2048
#define IN_DIM  4096
#define OUT_DIM 4096

__device__ __align__(256) __half g_W_h[(size_t)IN_DIM * OUT_DIM];   // [K,N] fp16
__device__ __align__(256) __half g_A_h[(size_t)BATCH * IN_DIM];     // [M,K] fp16
// FMA-column transpose: layout [k8][256 cols][8 halves] (16B per (k8,col))
__device__ __align__(256) __half g_Wt_h[(size_t)(IN_DIM / 8) * 256 * 8];
__device__ int g_ticket, g_fma_ticket, g_dec_ticket, g_a_done, g_chunks_done, g_done;
__device__ __align__(16) int g_slab_done[128];

#define NWORKERS 296
#define N_T 3840                 // tensor columns [0,3840); FMA [3840,4096)
#define BM 128
#define BN 64
#define BK 32
#define KT 128
#define NT_T ((BATCH / BM) * (N_T / BN))   // 16*60 = 960
#define NT_F (BATCH / 8)                   // 256 tiles (8 rows x 256 cols each)
#define STAGES 4
#define LDA_S 40
#define LDB_S 72
#define A_STAGE_H (BM * LDA_S)   // 5120
#define B_STAGE_H (BK * LDB_S)   // 2304
#define STAGE_H   (A_STAGE_H + B_STAGE_H)
#define SMEM_BYTES (STAGES * STAGE_H * 2)  // 59392

#define NDEC 128
#define NCHUNKS 512
#define CHUNK_INT4 8192
#define A_UNITS (BATCH * IN_DIM / 8)
#define A_PER_CTA ((A_UNITS + NWORKERS - 1) / NWORKERS)

__device__ __forceinline__ uint32_t smem_u32(const void* p) {
    uint32_t a;
    asm("{ .reg .u64 t; cvta.to.shared.u64 t, %1; cvt.u32.u64 %0, t; }" : "=r"(a) : "l"(p));
    return a;
}
__device__ __forceinline__ void cp_async16(__half* d, const __half* s) {
    uint32_t a = (uint32_t)__cvta_generic_to_shared(d);
    asm volatile("cp.async.cg.shared.global [%0], [%1], 16;\n" :: "r"(a), "l"(s));
}
__device__ __forceinline__ void mbar_init(uint32_t b, uint32_t c) {
    asm volatile("mbarrier.init.shared.b64 [%0], %1;" :: "r"(b), "r"(c) : "memory");
}
__device__ __forceinline__ void mbar_arrive(uint32_t b) {
    asm volatile("mbarrier.arrive.shared.b64 _, [%0];" :: "r"(b) : "memory");
}
__device__ __forceinline__ void cpasync_mbar_arrive(uint32_t b) {
    asm volatile("cp.async.mbarrier.arrive.noinc.shared.b64 [%0];" :: "r"(b) : "memory");
}
__device__ __forceinline__ void mbar_wait(uint32_t b, uint32_t par) {
    uint32_t done;
    asm volatile(
        "{\n\t.reg .pred p;\n\t"
        "mbarrier.try_wait.parity.acquire.cta.shared::cta.b64 p, [%1], %2;\n\t"
        "selp.b32 %0, 1, 0, p;\n\t}" : "=r"(done) : "r"(b), "r"(par) : "memory");
    if (!done) {
        asm volatile(
            "{\n\t.reg .pred P1;\n\t"
            "WL_%=:\n\t"
            "mbarrier.try_wait.parity.acquire.cta.shared::cta.b64 P1, [%0], %1, 0x989680;\n\t"
            "@P1 bra.uni WD_%=;\n\t"
            "bra.uni WL_%=;\n\t"
            "WD_%=:\n\t}" :: "r"(b), "r"(par) : "memory");
    }
}
__device__ __forceinline__ void named_bar(int id, int cnt) {
    asm volatile("bar.sync %0, %1;" :: "r"(id), "r"(cnt) : "memory");
}
__device__ __forceinline__ void ldmatrix_x4(uint32_t* r, const __half* p) {
    uint32_t a = (uint32_t)__cvta_generic_to_shared(p);
    asm volatile("ldmatrix.sync.aligned.m8n8.x4.shared.b16 {%0,%1,%2,%3}, [%4];"
                 : "=r"(r[0]), "=r"(r[1]), "=r"(r[2]), "=r"(r[3]) : "r"(a));
}
__device__ __forceinline__ void ldmatrix_x4_trans(uint32_t* r, const __half* p) {
    uint32_t a = (uint32_t)__cvta_generic_to_shared(p);
    asm volatile("ldmatrix.sync.aligned.m8n8.x4.trans.shared.b16 {%0,%1,%2,%3}, [%4];"
                 : "=r"(r[0]), "=r"(r[1]), "=r"(r[2]), "=r"(r[3]) : "r"(a));
}
__device__ __forceinline__ void mma_16816(float* d, const uint32_t* a, const uint32_t* b) {
    asm volatile(
        "mma.sync.aligned.m16n8k16.row.col.f32.f16.f16.f32 "
        "{%0,%1,%2,%3}, {%4,%5,%6,%7}, {%8,%9}, {%0,%1,%2,%3};"
        : "+f"(d[0]), "+f"(d[1]), "+f"(d[2]), "+f"(d[3])
        : "r"(a[0]), "r"(a[1]), "r"(a[2]), "r"(a[3]), "r"(b[0]), "r"(b[1]));
}
__device__ __forceinline__ int ld_acq(const int* p) {
    int v;
    asm volatile("ld.acquire.gpu.global.s32 %0, [%1];" : "=r"(v) : "l"(p) : "memory");
    return v;
}
__device__ __forceinline__ void spin_pause() { asm volatile("nanosleep.u32 64;" ::); }

__global__ __launch_bounds__(128, 2) void fused_kernel(
    const int4* __restrict__ idx, const float* __restrict__ mean,
    const float4* __restrict__ x, const float* __restrict__ bias,
    float* __restrict__ out)
{
    extern __shared__ __half smem[];
    __shared__ int s_tile_t, s_tile_f, s_chunk;
    __shared__ __align__(8) uint64_t s_mbar[2 * STAGES];
    __shared__ float s_mean[IN_DIM];

    const int cta = blockIdx.x;
    const int tid = threadIdx.x;
    const int lane = tid & 31;
    const int wid  = tid >> 5;

    // ---- Phase A: convert x -> fp16 (all CTAs) ----
    {
        const int u0 = cta * A_PER_CTA;
        const int u1 = (u0 + A_PER_CTA < A_UNITS) ? u0 + A_PER_CTA : A_UNITS;
        for (int u = u0 + tid; u < u1; u += 128) {
            float4 v0 = x[2 * u], v1 = x[2 * u + 1];
            __half2 h0 = __floats2half2_rn(v0.x, v0.y), h1 = __floats2half2_rn(v0.z, v0.w);
            __half2 h2 = __floats2half2_rn(v1.x, v1.y), h3 = __floats2half2_rn(v1.z, v1.w);
            uint4 pk;
            pk.x = *(uint32_t*)&h0; pk.y = *(uint32_t*)&h1;
            pk.z = *(uint32_t*)&h2; pk.w = *(uint32_t*)&h3;
            reinterpret_cast<uint4*>(g_A_h)[u] = pk;
        }
        __threadfence();
        __syncthreads();
        if (tid == 0) atomicAdd(&g_a_done, 1);
    }

    // ---- Phase W: decode (CTAs < NDEC); also writes g_Wt for FMA columns ----
    if (cta < NDEC) {
        for (int i = tid; i < IN_DIM; i += 128) s_mean[i] = mean[i];
        __syncthreads();
        while (true) {
            if (tid == 0) s_chunk = atomicAdd(&g_dec_ticket, 1);
            __syncthreads();
            const int cc = s_chunk;
            if (cc >= NCHUNKS) break;
            const size_t base = (size_t)cc * CHUNK_INT4 + tid;
            #pragma unroll 4
            for (int g = 0; g < CHUNK_INT4 / (128 * 4); g++) {
                #pragma unroll
                for (int j = 0; j < 4; j++) {
                    const int local = tid + (g * 4 + j) * 128;
                    int4 v = idx[base + (size_t)(g * 4 + j) * 128];
                    __half ha = __float2half_rn(s_mean[v.x]);
                    __half hb = __float2half_rn(s_mean[v.y]);
                    __half hc = __float2half_rn(s_mean[v.z]);
                    __half hd = __float2half_rn(s_mean[v.w]);
                    __half2 lo = __halves2half2(ha, hb), hi = __halves2half2(hc, hd);
                    uint2 pk;
                    pk.x = *(uint32_t*)&lo; pk.y = *(uint32_t*)&hi;
                    reinterpret_cast<uint2*>(g_W_h)[base + (size_t)(g * 4 + j) * 128] = pk;
                    const int n0 = (local & 1023) * 4;
                    if (n0 >= N_T) {
                        const int krow = cc * 8 + (local >> 10);
                        const size_t wb = ((size_t)(krow >> 3) * 256 + (n0 - N_T)) * 8 + (krow & 7);
                        g_Wt_h[wb]      = ha;
                        g_Wt_h[wb + 8]  = hb;
                        g_Wt_h[wb + 16] = hc;
                        g_Wt_h[wb + 24] = hd;
                    }
                }
            }
            __threadfence();
            __syncthreads();
            if (tid == 0) {
                atomicAdd(&g_slab_done[cc >> 2], 1);
                atomicAdd(&g_chunks_done, 1);
            }
        }
        __syncthreads();
    }

    // ---- mbarrier init (tensor ring, 64 arrivals), then role split ----
    const uint32_t mb = smem_u32(s_mbar);
    if (tid == 0) {
        #pragma unroll
        for (int s = 0; s < STAGES; s++) {
            mbar_init(mb + s * 8, 64);
            mbar_init(mb + (STAGES + s) * 8, 64);
        }
    }
    __syncthreads();

    while (ld_acq(&g_a_done) < NWORKERS) spin_pause();   // A ready (once)

    const bool flip = (cta >= 148);
    const bool is_tensor = ((wid >> 1) == (flip ? 1 : 0));

    if (is_tensor) {
        // =================== TENSOR: 2 warps, 128x64 tile ===================
        const int tw = wid & 1;
        const int ttid = tw * 32 + lane;
        const int lrow = lane & 15, lcol = (lane >> 4) * 8;
        auto full_bar  = [&](int s) -> uint32_t { return mb + s * 8; };
        auto empty_bar = [&](int s) -> uint32_t { return mb + (STAGES + s) * 8; };
        auto As = [&](int s) { return smem + s * STAGE_H; };
        auto Bs = [&](int s) { return smem + s * STAGE_H + A_STAGE_H; };
        int ps = 0, pp = 1, cs = 0, cp = 0;

        // Warp-level slab gate: lane 0 polls, warp gets broadcast. Free after
        // decode completes (wall cached).
        int wmax = -1; int wall = 0;
        auto gate_slab = [&](int s) {
            if (s <= wmax) return;
            if (lane == 0) {
                if (!wall && ld_acq(&g_chunks_done) >= NCHUNKS) wall = 1;
                if (!wall)
                    while (ld_acq(&g_slab_done[s]) < 4) spin_pause();
            }
            wall = __shfl_sync(0xffffffffu, wall, 0);
            wmax = wall ? 127 : s;
        };

        auto produce = [&](int kt, int row0, int col0) {
            gate_slab(kt);
            mbar_wait(empty_bar(ps), (uint32_t)pp);
            const __half* Ag = g_A_h + (size_t)row0 * IN_DIM + kt * BK;
            const __half* Bg = g_W_h + (size_t)(kt * BK) * OUT_DIM + col0;
            __half* as = As(ps);
            __half* bs = Bs(ps);
            #pragma unroll
            for (int p = 0; p < 8; p++) {
                int f = ttid + p * 64, r = f >> 2, c = (f & 3) * 8;
                cp_async16(&as[r * LDA_S + c], Ag + (size_t)r * IN_DIM + c);
            }
            #pragma unroll
            for (int p = 0; p < 4; p++) {
                int f = ttid + p * 64, r = f >> 3, c = (f & 7) * 8;
                cp_async16(&bs[r * LDB_S + c], Bg + (size_t)r * OUT_DIM + c);
            }
            cpasync_mbar_arrive(full_bar(ps));
            if (++ps == STAGES) { ps = 0; pp ^= 1; }
        };
        auto fetch = [&]() -> int {
            named_bar(2, 64);
            if (ttid == 0) s_tile_t = atomicAdd(&g_ticket, 1);
            named_bar(2, 64);
            return s_tile_t;
        };

        int t = fetch();
        if (t < NT_T) {
            int row0 = (t / 60) * BM, col0 = (t % 60) * BN;
            #pragma unroll
            for (int s = 0; s < STAGES - 1; s++) produce(s, row0, col0);
            while (true) {
                float acc[4][8][4];
                #pragma unroll
                for (int i = 0; i < 4; i++)
                    #pragma unroll
                    for (int j = 0; j < 8; j++)
                        #pragma unroll
                        for (int e = 0; e < 4; e++) acc[i][j][e] = 0.0f;

                for (int kt = 0; kt < KT; kt++) {
                    if (kt + STAGES - 1 < KT) produce(kt + STAGES - 1, row0, col0);
                    mbar_wait(full_bar(cs), (uint32_t)cp);
                    const __half* Asb = As(cs);
                    const __half* Bsb = Bs(cs);
                    uint32_t afr[2][4][4], bfr[2][4][4];
                    #pragma unroll
                    for (int ks = 0; ks < 2; ks++) {
                        #pragma unroll
                        for (int mt = 0; mt < 4; mt++)
                            ldmatrix_x4(afr[ks][mt],
                                Asb + (tw * 64 + mt * 16 + lrow) * LDA_S + ks * 16 + lcol);
                        #pragma unroll
                        for (int nt2 = 0; nt2 < 4; nt2++)
                            ldmatrix_x4_trans(bfr[ks][nt2],
                                Bsb + (ks * 16 + lrow) * LDB_S + nt2 * 16 + lcol);
                    }
                    mbar_arrive(empty_bar(cs));
                    if (++cs == STAGES) { cs = 0; cp ^= 1; }
                    #pragma unroll
                    for (int ks = 0; ks < 2; ks++)
                        #pragma unroll
                        for (int mt = 0; mt < 4; mt++)
                            #pragma unroll
                            for (int nt = 0; nt < 8; nt++)
                                mma_16816(acc[mt][nt], afr[ks][mt],
                                          &bfr[ks][nt >> 1][(nt & 1) * 2]);
                }

                const int erow0 = row0, ecol0 = col0;
                int t2 = fetch();
                const bool more = (t2 < NT_T);
                if (more) {
                    row0 = (t2 / 60) * BM; col0 = (t2 % 60) * BN;
                    #pragma unroll
                    for (int s = 0; s < STAGES - 1; s++) produce(s, row0, col0);
                }
                #pragma unroll
                for (int mt = 0; mt < 4; mt++) {
                    const int r = erow0 + tw * 64 + mt * 16 + (lane >> 2);
                    float* o0 = out + (size_t)r * OUT_DIM;
                    float* o1 = out + (size_t)(r + 8) * OUT_DIM;
                    #pragma unroll
                    for (int nt = 0; nt < 8; nt++) {
                        const int c = ecol0 + nt * 8 + 2 * (lane & 3);
                        float2 bb = *reinterpret_cast<const float2*>(bias + c);
                        float2 v0 = { acc[mt][nt][0] + bb.x, acc[mt][nt][1] + bb.y };
                        float2 v1 = { acc[mt][nt][2] + bb.x, acc[mt][nt][3] + bb.y };
                        *reinterpret_cast<float2*>(o0 + c) = v0;
                        *reinterpret_cast<float2*>(o1 + c) = v1;
                    }
                }
                if (!more) break;
            }
        }
    } else {
        // =================== FMA: 2 warps, cols [3840,4096) =================
        // Wait ONCE for full decode, then run gate-free (budget >> decode time).
        const int fw = wid & 1;
        const int colrel = fw * 128 + lane;
        const uint4* Wt4 = reinterpret_cast<const uint4*>(g_Wt_h);
        if (lane == 0)
            while (ld_acq(&g_chunks_done) < NCHUNKS) spin_pause();
        __syncwarp();

        while (true) {
            named_bar(3, 64);
            if (fw == 0 && lane == 0) s_tile_f = atomicAdd(&g_fma_ticket, 1);
            named_bar(3, 64);
            const int t = s_tile_f;
            if (t >= NT_F) break;
            const int r0 = t * 8;

            float accf[8][4];
            #pragma unroll
            for (int r = 0; r < 8; r++)
                #pragma unroll
                for (int ci = 0; ci < 4; ci++) accf[r][ci] = 0.0f;

            for (int kc = 0; kc < 128; kc++) {      // 32-k fp16 chains
                __half2 acch[8][4];
                #pragma unroll
                for (int r = 0; r < 8; r++)
                    #pragma unroll
                    for (int ci = 0; ci < 4; ci++)
                        acch[r][ci] = __float2half2_rn(0.0f);
                #pragma unroll
                for (int k8 = 0; k8 < 4; k8++) {
                    const int k0 = kc * 32 + k8 * 8;
                    uint4 b4[4], a4[8];
                    #pragma unroll
                    for (int ci = 0; ci < 4; ci++)
                        b4[ci] = __ldg(&Wt4[(size_t)(k0 >> 3) * 256 + colrel + ci * 32]);
                    #pragma unroll
                    for (int r = 0; r < 8; r++)
                        a4[r] = __ldg(reinterpret_cast<const uint4*>(
                                    g_A_h + (size_t)(r0 + r) * IN_DIM + k0));
                    #pragma unroll
                    for (int k2 = 0; k2 < 4; k2++)
                        #pragma unroll
                        for (int r = 0; r < 8; r++) {
                            const __half2 a2 = reinterpret_cast<const __half2*>(&a4[r])[k2];
                            #pragma unroll
                            for (int ci = 0; ci < 4; ci++)
                                acch[r][ci] = __hfma2(a2,
                                    reinterpret_cast<const __half2*>(&b4[ci])[k2],
                                    acch[r][ci]);
                        }
                }
                #pragma unroll
                for (int r = 0; r < 8; r++)
                    #pragma unroll
                    for (int ci = 0; ci < 4; ci++) {
                        float2 f = __half22float2(acch[r][ci]);
                        accf[r][ci] += f.x + f.y;
                    }
            }
            #pragma unroll
            for (int ci = 0; ci < 4; ci++) {
                const int c = N_T + colrel + ci * 32;
                const float bb = __ldg(bias + c);
                #pragma unroll
                for (int r = 0; r < 8; r++)
                    out[(size_t)(r0 + r) * OUT_DIM + c] = accf[r][ci] + bb;
            }
        }
    }

    // ---- Reset (last CTA out) ----
    __syncthreads();
    if (tid == 0) {
        __threadfence();
        int d = atomicAdd(&g_done, 1);
        if (d == NWORKERS - 1) {
            g_ticket = 0; g_fma_ticket = 0; g_dec_ticket = 0;
            g_a_done = 0; g_chunks_done = 0;
            #pragma unroll
            for (int s = 0; s < 128; s++) g_slab_done[s] = 0;
            __threadfence();
            g_done = 0;
            __threadfence();
        }
    }
}

extern "C" void kernel_launch(void* const* d_in, const int* in_sizes, int n_in,
                              void* d_out, int out_size) {
    const float* xf   = (const float*)d_in[0];
    const int*   idx  = (const int*)  d_in[1];
    const float* mean = (const float*)d_in[2];
    const float* bias = (const float*)d_in[3];
    float* out = (float*)d_out;

    cudaFuncSetAttribute(fused_kernel,
                         cudaFuncAttributeMaxDynamicSharedMemorySize, SMEM_BYTES);
    fused_kernel<<<NWORKERS, 128, SMEM_BYTES>>>(
        (const int4*)idx, mean, (const float4*)xf, bias, out);
}

// round 17
// speedup vs baseline: 1.6641x; 1.3807x over previous
#include <cuda_runtime.h>
#include <cuda_fp16.h>
#include <cstdint>

#define BATCH   2048
#define IN_DIM  4096
#define OUT_DIM 4096

__device__ __align__(256) __half g_W_h[(size_t)IN_DIM * OUT_DIM];  // [K,N] fp16
__device__ __align__(256) __half g_A_h[(size_t)BATCH * IN_DIM];    // [M,K] fp16
__device__ int g_ticket, g_dec_ticket, g_a_done, g_chunks_done, g_done;
__device__ __align__(16) int g_slab_done[128];

#define BM 128
#define BN 64
#define BK 32
#define KT (IN_DIM / BK)        // 128
#define NTILES ((BATCH / BM) * (OUT_DIM / BN))   // 16*64 = 1024
#define NWORKERS 296
#define STAGES 4
#define LDA_S 40                // A smem row stride (halves): 80B
#define LDB_S 72                // B smem row stride (halves): 144B
#define A_STAGE_H (BM * LDA_S)  // 5120
#define B_STAGE_H (BK * LDB_S)  // 2304
#define STAGE_H   (A_STAGE_H + B_STAGE_H)        // 7424
#define SMEM_BYTES (STAGES * STAGE_H * 2)        // 59392 B

#define NDEC 128
#define NCHUNKS 512
#define CHUNK_INT4 (8 * OUT_DIM / 4)     // 8192
#define A_UNITS (BATCH * IN_DIM / 8)
#define A_PER_CTA ((A_UNITS + NWORKERS - 1) / NWORKERS)

__device__ __forceinline__ uint32_t smem_u32(const void* p) {
    uint32_t a;
    asm("{ .reg .u64 t; cvta.to.shared.u64 t, %1; cvt.u32.u64 %0, t; }" : "=r"(a) : "l"(p));
    return a;
}
__device__ __forceinline__ void cp_async16(__half* d, const __half* s) {
    uint32_t a = (uint32_t)__cvta_generic_to_shared(d);
    asm volatile("cp.async.cg.shared.global [%0], [%1], 16;\n" :: "r"(a), "l"(s));
}
__device__ __forceinline__ void mbar_init(uint32_t b, uint32_t c) {
    asm volatile("mbarrier.init.shared.b64 [%0], %1;" :: "r"(b), "r"(c) : "memory");
}
__device__ __forceinline__ void mbar_arrive(uint32_t b) {
    asm volatile("mbarrier.arrive.shared.b64 _, [%0];" :: "r"(b) : "memory");
}
__device__ __forceinline__ void cpasync_mbar_arrive(uint32_t b) {
    asm volatile("cp.async.mbarrier.arrive.noinc.shared.b64 [%0];" :: "r"(b) : "memory");
}
__device__ __forceinline__ void mbar_wait(uint32_t b, uint32_t par) {
    uint32_t done;
    asm volatile(
        "{\n\t.reg .pred p;\n\t"
        "mbarrier.try_wait.parity.acquire.cta.shared::cta.b64 p, [%1], %2;\n\t"
        "selp.b32 %0, 1, 0, p;\n\t}" : "=r"(done) : "r"(b), "r"(par) : "memory");
    if (!done) {
        asm volatile(
            "{\n\t.reg .pred P1;\n\t"
            "WL_%=:\n\t"
            "mbarrier.try_wait.parity.acquire.cta.shared::cta.b64 P1, [%0], %1, 0x989680;\n\t"
            "@P1 bra.uni WD_%=;\n\t"
            "bra.uni WL_%=;\n\t"
            "WD_%=:\n\t}" :: "r"(b), "r"(par) : "memory");
    }
}
__device__ __forceinline__ void ldmatrix_x4(uint32_t* r, const __half* p) {
    uint32_t a = (uint32_t)__cvta_generic_to_shared(p);
    asm volatile("ldmatrix.sync.aligned.m8n8.x4.shared.b16 {%0,%1,%2,%3}, [%4];"
                 : "=r"(r[0]), "=r"(r[1]), "=r"(r[2]), "=r"(r[3]) : "r"(a));
}
__device__ __forceinline__ void ldmatrix_x4_trans(uint32_t* r, const __half* p) {
    uint32_t a = (uint32_t)__cvta_generic_to_shared(p);
    asm volatile("ldmatrix.sync.aligned.m8n8.x4.trans.shared.b16 {%0,%1,%2,%3}, [%4];"
                 : "=r"(r[0]), "=r"(r[1]), "=r"(r[2]), "=r"(r[3]) : "r"(a));
}
__device__ __forceinline__ void mma_16816(float* d, const uint32_t* a, const uint32_t* b) {
    asm volatile(
        "mma.sync.aligned.m16n8k16.row.col.f32.f16.f16.f32 "
        "{%0,%1,%2,%3}, {%4,%5,%6,%7}, {%8,%9}, {%0,%1,%2,%3};"
        : "+f"(d[0]), "+f"(d[1]), "+f"(d[2]), "+f"(d[3])
        : "r"(a[0]), "r"(a[1]), "r"(a[2]), "r"(a[3]), "r"(b[0]), "r"(b[1]));
}
__device__ __forceinline__ int ld_acq(const int* p) {
    int v;
    asm volatile("ld.acquire.gpu.global.s32 %0, [%1];" : "=r"(v) : "l"(p) : "memory");
    return v;
}
__device__ __forceinline__ void spin_pause() { asm volatile("nanosleep.u32 64;" ::); }

__global__ __launch_bounds__(128, 2) void fused_kernel(
    const int4*   __restrict__ idx,
    const float*  __restrict__ mean,
    const float4* __restrict__ x,
    const float*  __restrict__ bias,
    float*        __restrict__ out)
{
    extern __shared__ __half smem[];
    __shared__ int s_tile;
    __shared__ int s_chunk;
    __shared__ __align__(8) uint64_t s_mbar[2 * STAGES];
    __shared__ float s_mean[IN_DIM];

    const int cta  = blockIdx.x;
    const int tid  = threadIdx.x;
    const int lane = tid & 31;
    const int warpId = tid >> 5;
    const int wm = warpId >> 1;   // M offset wm*64
    const int wn = warpId & 1;    // N offset wn*32
    const int lrow = lane & 15;
    const int lcol = (lane >> 4) * 8;

    // ---- Phase A: convert x -> fp16 ----
    {
        const int u0 = cta * A_PER_CTA;
        const int u1 = (u0 + A_PER_CTA < A_UNITS) ? u0 + A_PER_CTA : A_UNITS;
        for (int u = u0 + tid; u < u1; u += 128) {
            float4 v0 = x[2 * u], v1 = x[2 * u + 1];
            __half2 h0 = __floats2half2_rn(v0.x, v0.y), h1 = __floats2half2_rn(v0.z, v0.w);
            __half2 h2 = __floats2half2_rn(v1.x, v1.y), h3 = __floats2half2_rn(v1.z, v1.w);
            uint4 pk;
            pk.x = *(uint32_t*)&h0; pk.y = *(uint32_t*)&h1;
            pk.z = *(uint32_t*)&h2; pk.w = *(uint32_t*)&h3;
            reinterpret_cast<uint4*>(g_A_h)[u] = pk;
        }
        __threadfence();
        __syncthreads();
        if (tid == 0) atomicAdd(&g_a_done, 1);
    }

    // ---- Phase W: decode (CTAs < NDEC), k-ordered chunks ----
    if (cta < NDEC) {
        for (int i = tid; i < IN_DIM; i += 128) s_mean[i] = mean[i];
        __syncthreads();
        while (true) {
            if (tid == 0) s_chunk = atomicAdd(&g_dec_ticket, 1);
            __syncthreads();
            const int c = s_chunk;
            if (c >= NCHUNKS) break;
            const size_t base = (size_t)c * CHUNK_INT4 + tid;
            #pragma unroll 4
            for (int g = 0; g < CHUNK_INT4 / (128 * 4); g++) {
                int4 v[4];
                #pragma unroll
                for (int j = 0; j < 4; j++) v[j] = idx[base + (size_t)(g * 4 + j) * 128];
                #pragma unroll
                for (int j = 0; j < 4; j++) {
                    __half2 lo = __floats2half2_rn(s_mean[v[j].x], s_mean[v[j].y]);
                    __half2 hi = __floats2half2_rn(s_mean[v[j].z], s_mean[v[j].w]);
                    uint2 pk;
                    pk.x = *(uint32_t*)&lo; pk.y = *(uint32_t*)&hi;
                    reinterpret_cast<uint2*>(g_W_h)[base + (size_t)(g * 4 + j) * 128] = pk;
                }
            }
            __threadfence();
            __syncthreads();
            if (tid == 0) {
                atomicAdd(&g_slab_done[c >> 2], 1);
                atomicAdd(&g_chunks_done, 1);
            }
        }
        __syncthreads();
    }

    // ---- GEMM: mbarrier warp-skew pipeline ----
    const uint32_t mb = smem_u32(s_mbar);
    auto full_bar  = [&](int s) -> uint32_t { return mb + s * 8; };
    auto empty_bar = [&](int s) -> uint32_t { return mb + (STAGES + s) * 8; };

    if (tid == 0) {
        #pragma unroll
        for (int s = 0; s < STAGES; s++) {
            mbar_init(full_bar(s), 128);
            mbar_init(empty_bar(s), 128);
        }
    }
    __syncthreads();

    auto As = [&](int s) { return smem + s * STAGE_H; };
    auto Bs = [&](int s) { return smem + s * STAGE_H + A_STAGE_H; };

    int prod_stage = 0, prod_phase = 1;
    int cons_stage = 0, cons_phase = 0;

    // tid0-only gating (cached)
    bool a_rdy = false, w_all = false;
    int wmax = -1;
    auto ensure_a = [&]() {
        if (a_rdy) return;
        while (ld_acq(&g_a_done) < NWORKERS) spin_pause();
        a_rdy = true;
    };
    auto ensure_slab = [&](int s) {
        if (w_all || s <= wmax) return;
        if (ld_acq(&g_chunks_done) >= NCHUNKS) { w_all = true; return; }
        while (wmax < s) {
            if (ld_acq(&g_slab_done[wmax + 1]) >= 4) { wmax++; }
            else spin_pause();
        }
    };

    auto produce = [&](int kt, int row0, int col0) {
        mbar_wait(empty_bar(prod_stage), (uint32_t)prod_phase);
        const __half* Ag = g_A_h + (size_t)row0 * IN_DIM + kt * BK;
        const __half* Bg = g_W_h + (size_t)(kt * BK) * OUT_DIM + col0;
        __half* as = As(prod_stage);
        __half* bs = Bs(prod_stage);
        // A: 128 rows x 4 chunks of 8 halves = 512 chunks (4/thread)
        #pragma unroll
        for (int p = 0; p < 4; p++) {
            int f = tid + p * 128;
            int r = f >> 2, c = (f & 3) * 8;
            cp_async16(&as[r * LDA_S + c], Ag + (size_t)r * IN_DIM + c);
        }
        // B: 32 rows x 8 chunks of 8 halves = 256 chunks (2/thread)
        #pragma unroll
        for (int p = 0; p < 2; p++) {
            int f = tid + p * 128;
            int r = f >> 3, c = (f & 7) * 8;
            cp_async16(&bs[r * LDB_S + c], Bg + (size_t)r * OUT_DIM + c);
        }
        cpasync_mbar_arrive(full_bar(prod_stage));
        if (++prod_stage == STAGES) { prod_stage = 0; prod_phase ^= 1; }
    };

    auto fetch_ticket = [&]() -> int {
        __syncthreads();
        if (tid == 0) s_tile = atomicAdd(&g_ticket, 1);
        __syncthreads();
        return s_tile;
    };

    int t = fetch_ticket();
    if (t < NTILES) {
        int row0 = (t >> 6) * BM;
        int col0 = (t & 63) * BN;

        if (tid == 0) { ensure_a(); ensure_slab(STAGES - 2); }
        __syncthreads();
        #pragma unroll
        for (int s = 0; s < STAGES - 1; s++) produce(s, row0, col0);

        while (true) {
            float acc[4][4][4];
            #pragma unroll
            for (int i = 0; i < 4; i++)
                #pragma unroll
                for (int j = 0; j < 4; j++)
                    #pragma unroll
                    for (int e = 0; e < 4; e++) acc[i][j][e] = 0.0f;

            for (int kt = 0; kt < KT; kt++) {
                if (kt + STAGES - 1 < KT) {
                    if (tid == 0) ensure_slab(kt + STAGES - 1);
                    produce(kt + STAGES - 1, row0, col0);
                }

                mbar_wait(full_bar(cons_stage), (uint32_t)cons_phase);
                const __half* Asb = As(cons_stage);
                const __half* Bsb = Bs(cons_stage);

                uint32_t afr[2][4][4];
                uint32_t bfr[2][2][4];
                #pragma unroll
                for (int ks = 0; ks < 2; ks++) {
                    #pragma unroll
                    for (int mt = 0; mt < 4; mt++)
                        ldmatrix_x4(afr[ks][mt],
                            Asb + (wm * 64 + mt * 16 + lrow) * LDA_S + ks * 16 + lcol);
                    #pragma unroll
                    for (int nt2 = 0; nt2 < 2; nt2++)
                        ldmatrix_x4_trans(bfr[ks][nt2],
                            Bsb + (ks * 16 + lrow) * LDB_S + wn * 32 + nt2 * 16 + lcol);
                }
                mbar_arrive(empty_bar(cons_stage));
                if (++cons_stage == STAGES) { cons_stage = 0; cons_phase ^= 1; }

                #pragma unroll
                for (int ks = 0; ks < 2; ks++)
                    #pragma unroll
                    for (int mt = 0; mt < 4; mt++)
                        #pragma unroll
                        for (int nt = 0; nt < 4; nt++)
                            mma_16816(acc[mt][nt], afr[ks][mt],
                                      &bfr[ks][nt >> 1][(nt & 1) * 2]);
            }

            const int erow0 = row0, ecol0 = col0;
            int t2 = fetch_ticket();
            const bool more = (t2 < NTILES);
            if (more) {
                row0 = (t2 >> 6) * BM;
                col0 = (t2 & 63) * BN;
                #pragma unroll
                for (int s = 0; s < STAGES - 1; s++) produce(s, row0, col0);
            }

            // Epilogue: direct float2 stores with fused bias.
            #pragma unroll
            for (int mt = 0; mt < 4; mt++) {
                const int r = erow0 + wm * 64 + mt * 16 + (lane >> 2);
                float* o0 = out + (size_t)r * OUT_DIM;
                float* o1 = out + (size_t)(r + 8) * OUT_DIM;
                #pragma unroll
                for (int nt = 0; nt < 4; nt++) {
                    const int c = ecol0 + wn * 32 + nt * 8 + 2 * (lane & 3);
                    float2 bb = *reinterpret_cast<const float2*>(bias + c);
                    float2 v0 = { acc[mt][nt][0] + bb.x, acc[mt][nt][1] + bb.y };
                    float2 v1 = { acc[mt][nt][2] + bb.x, acc[mt][nt][3] + bb.y };
                    *reinterpret_cast<float2*>(o0 + c) = v0;
                    *reinterpret_cast<float2*>(o1 + c) = v1;
                }
            }

            if (!more) break;
        }
    }

    // ---- Reset (last CTA out) ----
    __syncthreads();
    if (tid == 0) {
        __threadfence();
        int d = atomicAdd(&g_done, 1);
        if (d == NWORKERS - 1) {
            g_ticket = 0; g_dec_ticket = 0;
            g_a_done = 0; g_chunks_done = 0;
            #pragma unroll
            for (int s = 0; s < KT; s++) g_slab_done[s] = 0;
            __threadfence();
            g_done = 0;
            __threadfence();
        }
    }
}

extern "C" void kernel_launch(void* const* d_in, const int* in_sizes, int n_in,
                              void* d_out, int out_size) {
    const float* xf   = (const float*)d_in[0];
    const int*   idx  = (const int*)  d_in[1];
    const float* mean = (const float*)d_in[2];
    const float* bias = (const float*)d_in[3];
    float* out = (float*)d_out;

    cudaFuncSetAttribute(fused_kernel,
                         cudaFuncAttributeMaxDynamicSharedMemorySize, SMEM_BYTES);
    fused_kernel<<<NWORKERS, 128, SMEM_BYTES>>>(
        (const int4*)idx, mean, (const float4*)xf, bias, out);
}